// round 15
// baseline (speedup 1.0000x reference)
#include <cuda_runtime.h>
#include <cuda_fp16.h>
#include <math.h>
#include <stdint.h>

#define NTOK 4096
#define DIM 768
#define QKVN (3*DIM)
#define FFD 3072
#define NE 8
#define NPAIR (NTOK*2)
#define TSEQ 1024
#define NB 4
#define NH 12
#define HD 64

// split GEMM: A swizzled 64B rows (hi/lo), B native [k][n] 272B rows (hi/lo), BK=32, 3 stages
#define SBKE 32
#define SAREG 8192
#define SBREG (32*272)
#define SSTGB (2*SAREG + 2*SBREG)       // 33792
#define GSMEM_SPLIT (3*SSTGB)           // 101376

// MoE GEMM: BK=64. A 128x144B + B-trans 64x272B, 3 stages
#define MBKE 64
#define MAREG (128*144)                 // 18432
#define MBREG (64*272)                  // 17408
#define MSTGB (MAREG + MBREG)           // 35840
#define GSMEM_MOE (3*MSTGB)             // 107520

// attention: Q 128x64 hi/lo + double-buffered KV
#define AT_ROWB 144
#define AT_QL   (128*AT_ROWB)
#define AT_KV0  (2*128*AT_ROWB)
#define KVBUF   (4*64*AT_ROWB)
#define AT_SMEM (AT_KV0 + 2*KVBUF)      // 110592

struct Scratch {
  float x1[(size_t)NTOK*DIM];
  __half qkvh[(size_t)NTOK*QKVN], qkvl[(size_t)NTOK*QKVN];
  __half xln1h[(size_t)NTOK*DIM], xln1l[(size_t)NTOK*DIM];
  __half attnh[(size_t)NTOK*DIM], attnl[(size_t)NTOK*DIM];
  __half xln2h[(size_t)NTOK*DIM];
  __half Hh[(size_t)NPAIR*FFD];          // dense slot order
  __half Wqkvh[(size_t)DIM*QKVN], Wqkvl[(size_t)DIM*QKVN];
  __half Wprojh[(size_t)DIM*DIM], Wprojl[(size_t)DIM*DIM];
  __half W1h[(size_t)NE*DIM*FFD];
  __half W2h[(size_t)NE*FFD*DIM];
  float pairw[NPAIR];
  int bucket[NE*NPAIR];
  int count[NE];
};
__device__ Scratch g_s;

__device__ __forceinline__ float gelu_f(float v) {
  return 0.5f * v * (1.0f + erff(v * 0.70710678118654752f));
}
__device__ __forceinline__ uint32_t smem_u32(const void* p) {
  uint32_t a;
  asm("{ .reg .u64 t; cvta.to.shared.u64 t, %1; cvt.u32.u64 %0, t; }" : "=r"(a) : "l"(p));
  return a;
}
__device__ __forceinline__ void cp16(uint32_t dst, const void* src) {
  asm volatile("cp.async.cg.shared.global [%0], [%1], 16;\n" :: "r"(dst), "l"(src));
}
__device__ __forceinline__ void cp_commit() { asm volatile("cp.async.commit_group;\n"); }
template<int N> __device__ __forceinline__ void cp_wait() {
  asm volatile("cp.async.wait_group %0;\n" :: "n"(N));
}
__device__ __forceinline__ void ldsm4(uint32_t* r, uint32_t addr) {
  asm volatile("ldmatrix.sync.aligned.m8n8.x4.shared.b16 {%0,%1,%2,%3}, [%4];"
    : "=r"(r[0]), "=r"(r[1]), "=r"(r[2]), "=r"(r[3]) : "r"(addr));
}
__device__ __forceinline__ void ldsm4t(uint32_t* r, uint32_t addr) {
  asm volatile("ldmatrix.sync.aligned.m8n8.x4.trans.shared.b16 {%0,%1,%2,%3}, [%4];"
    : "=r"(r[0]), "=r"(r[1]), "=r"(r[2]), "=r"(r[3]) : "r"(addr));
}
__device__ __forceinline__ void mma_f16(float* c, const uint32_t* a, const uint32_t* b) {
  asm volatile(
    "mma.sync.aligned.m16n8k16.row.col.f32.f16.f16.f32 "
    "{%0,%1,%2,%3},{%4,%5,%6,%7},{%8,%9},{%0,%1,%2,%3};\n"
    : "+f"(c[0]), "+f"(c[1]), "+f"(c[2]), "+f"(c[3])
    : "r"(a[0]), "r"(a[1]), "r"(a[2]), "r"(a[3]), "r"(b[0]), "r"(b[1]));
}
__device__ __forceinline__ uint32_t packh2(float x, float y) {
  __half2 h; h.x = __float2half_rn(x); h.y = __float2half_rn(y);
  return *(uint32_t*)&h;
}
__device__ __forceinline__ uint32_t swz(int row, int c) {
  return (uint32_t)(row*64 + ((c ^ ((row >> 1) & 3)) << 4));
}

// ==== split-3 fp16 GEMM: A swizzled, B native [k][n] via ldsm4t, 3-stage ====
template<int MODE>
__global__ __launch_bounds__(256, 2)
void gemm_split(const __half* __restrict__ Ahg, const __half* __restrict__ Alg,
                const __half* __restrict__ Bhg, const __half* __restrict__ Blg,
                float* __restrict__ Cf, __half* __restrict__ Chalf, __half* __restrict__ Chalf2,
                int M, int N, int K, const float* __restrict__ resid)
{
  extern __shared__ char dynsm[];
  int tid = threadIdx.x, wid = tid >> 5, lane = tid & 31;
  int m0 = blockIdx.y * 128;
  int n0 = blockIdx.x * 128;
  uint32_t sbase = smem_u32(dynsm);

  auto load_chunk = [&](int stage, int k0) {
    uint32_t st = sbase + stage * SSTGB;
    #pragma unroll
    for (int i = 0; i < 2; i++) {
      int u = tid + i*256;
      int row = u >> 2, c = u & 3;
      uint32_t so = swz(row, c);
      size_t go = (size_t)(m0 + row) * K + k0 + c*8;
      cp16(st + so,         Ahg + go);
      cp16(st + SAREG + so, Alg + go);
    }
    #pragma unroll
    for (int i = 0; i < 2; i++) {
      int u = tid + i*256;
      int row = u >> 4, c = u & 15;
      uint32_t so = (uint32_t)(row*272 + c*16);
      size_t go = (size_t)(k0 + row) * N + n0 + c*8;
      cp16(st + 2*SAREG + so,         Bhg + go);
      cp16(st + 2*SAREG + SBREG + so, Blg + go);
    }
    cp_commit();
  };

  int wm = wid >> 1, wn = wid & 1;
  int arow = wm*32 + (lane & 15);
  int acs  = (lane >> 4);
  uint32_t btoff = (uint32_t)((lane & 15)*272 + wn*128 + ((lane >> 4) << 4));

  float acc[2][8][4];
  #pragma unroll
  for (int i = 0; i < 2; i++)
    #pragma unroll
    for (int j = 0; j < 8; j++)
      #pragma unroll
      for (int q = 0; q < 4; q++) acc[i][j][q] = 0.f;

  auto compute = [&](int stage) {
    uint32_t st = sbase + stage * SSTGB;
    uint32_t bbh = st + 2*SAREG;
    uint32_t bbl = bbh + SBREG;
    #pragma unroll
    for (int ks = 0; ks < 2; ks++) {
      uint32_t ah[2][4], al[2][4];
      ldsm4(ah[0], st +         swz(arow,      acs + ks*2));
      ldsm4(ah[1], st +         swz(arow + 16, acs + ks*2));
      ldsm4(al[0], st + SAREG + swz(arow,      acs + ks*2));
      ldsm4(al[1], st + SAREG + swz(arow + 16, acs + ks*2));
      #pragma unroll
      for (int g = 0; g < 4; g++) {
        uint32_t bh[4], bl[4];
        ldsm4t(bh, bbh + btoff + ks*16*272 + g*32);
        ldsm4t(bl, bbl + btoff + ks*16*272 + g*32);
        #pragma unroll
        for (int t = 0; t < 2; t++) {
          #pragma unroll
          for (int mt = 0; mt < 2; mt++) {
            float* c = acc[mt][g*2 + t];
            mma_f16(c, ah[mt], bl + t*2);
            mma_f16(c, al[mt], bh + t*2);
            mma_f16(c, ah[mt], bh + t*2);
          }
        }
      }
    }
  };

  int nkt = K / SBKE;
  load_chunk(0, 0);
  if (nkt > 1) load_chunk(1, SBKE);
  for (int kt = 0; kt < nkt; kt++) {
    if (kt + 1 < nkt) cp_wait<1>(); else cp_wait<0>();
    __syncthreads();
    if (kt + 2 < nkt) load_chunk((kt + 2) % 3, (kt + 2) * SBKE);
    compute(kt % 3);
  }

  #pragma unroll
  for (int mt = 0; mt < 2; mt++) {
    #pragma unroll
    for (int half = 0; half < 2; half++) {
      int gmi = m0 + wm*32 + mt*16 + (lane >> 2) + half*8;
      #pragma unroll
      for (int nt = 0; nt < 8; nt++) {
        int col = n0 + wn*64 + nt*8 + (lane & 3)*2;
        float v0 = acc[mt][nt][half*2 + 0];
        float v1 = acc[mt][nt][half*2 + 1];
        if constexpr (MODE == 0) {
          float sc = (col < DIM) ? 0.125f : 1.0f;
          v0 *= sc; v1 *= sc;
          __half h0 = __float2half_rn(v0), h1 = __float2half_rn(v1);
          __half2 hv; hv.x = h0; hv.y = h1;
          __half2 lv;
          lv.x = __float2half_rn(v0 - __half2float(h0));
          lv.y = __float2half_rn(v1 - __half2float(h1));
          *(__half2*)(Chalf + (size_t)gmi * N + col) = hv;
          *(__half2*)(Chalf2 + (size_t)gmi * N + col) = lv;
        } else {
          const float* rp = resid + (size_t)gmi * N + col;
          *(float2*)(Cf + (size_t)gmi * N + col) = make_float2(v0 + rp[0], v1 + rp[1]);
        }
      }
    }
  }
}

// ============ MoE UP: gather A by token, write H in DENSE slot order ============
__global__ __launch_bounds__(256, 2)
void gemm_moe_up(const __half* __restrict__ Ahg, const __half* __restrict__ Bhg,
                 __half* __restrict__ Hh, int N, int K,
                 const int* __restrict__ bucket, const int* __restrict__ counts)
{
  extern __shared__ char dynsm[];
  __shared__ int sPair[128];
  int tid = threadIdx.x, wid = tid >> 5, lane = tid & 31;
  int e = blockIdx.z;
  int mcount = counts[e];
  int m0 = blockIdx.y * 128;
  if (m0 >= mcount) return;
  int offe = 0;
  for (int i = 0; i < NE; i++) offe += (i < e) ? counts[i] : 0;
  int n0 = blockIdx.x * 128;
  Bhg += (size_t)e * K * N;
  if (tid < 128) {
    int gm = m0 + tid;
    sPair[tid] = bucket[e * NPAIR + (gm < mcount ? gm : mcount - 1)];
  }
  __syncthreads();

  uint32_t sbase = smem_u32(dynsm);

  int arow4[4];
  #pragma unroll
  for (int i = 0; i < 4; i++) {
    int row = (tid + i*256) >> 3;
    arow4[i] = sPair[row] >> 1;
  }

  auto load_chunk = [&](int stage, int k0) {
    uint32_t st = sbase + stage * MSTGB;
    #pragma unroll
    for (int i = 0; i < 4; i++) {
      int u = tid + i*256;
      int row = u >> 3, c = u & 7;
      cp16(st + row*144 + c*16, Ahg + (size_t)arow4[i] * K + k0 + c*8);
    }
    #pragma unroll
    for (int i = 0; i < 4; i++) {
      int u = tid + i*256;
      int row = u >> 4, c = u & 15;
      cp16(st + MAREG + row*272 + c*16, Bhg + (size_t)(k0 + row) * N + n0 + c*8);
    }
    cp_commit();
  };

  int wm = wid >> 1, wn = wid & 1;
  uint32_t aoff  = (uint32_t)((wm*32 + (lane & 15))*144 + ((lane >> 4) << 4));
  uint32_t btoff = (uint32_t)((lane & 15)*272 + wn*128 + ((lane >> 4) << 4));

  float acc[2][8][4];
  #pragma unroll
  for (int i = 0; i < 2; i++)
    #pragma unroll
    for (int j = 0; j < 8; j++)
      #pragma unroll
      for (int q = 0; q < 4; q++) acc[i][j][q] = 0.f;

  auto compute = [&](int stage) {
    uint32_t st = sbase + stage * MSTGB;
    uint32_t bb = st + MAREG;
    #pragma unroll
    for (int ks = 0; ks < 4; ks++) {
      uint32_t ah[2][4];
      ldsm4(ah[0], st + aoff + ks*32);
      ldsm4(ah[1], st + aoff + 16*144 + ks*32);
      #pragma unroll
      for (int g = 0; g < 4; g++) {
        uint32_t bh[4];
        ldsm4t(bh, bb + btoff + ks*16*272 + g*32);
        #pragma unroll
        for (int t = 0; t < 2; t++) {
          #pragma unroll
          for (int mt = 0; mt < 2; mt++)
            mma_f16(acc[mt][g*2 + t], ah[mt], bh + t*2);
        }
      }
    }
  };

  int nkt = K / MBKE;
  load_chunk(0, 0);
  if (nkt > 1) load_chunk(1, MBKE);
  for (int kt = 0; kt < nkt; kt++) {
    if (kt + 1 < nkt) cp_wait<1>(); else cp_wait<0>();
    __syncthreads();
    if (kt + 2 < nkt) load_chunk((kt + 2) % 3, (kt + 2) * MBKE);
    compute(kt % 3);
  }

  #pragma unroll
  for (int mt = 0; mt < 2; mt++) {
    #pragma unroll
    for (int half = 0; half < 2; half++) {
      int rl = wm*32 + mt*16 + (lane >> 2) + half*8;
      int gmi = m0 + rl;
      if (gmi < mcount) {
        int drow = offe + gmi;     // dense slot
        #pragma unroll
        for (int nt = 0; nt < 8; nt++) {
          int col = n0 + wn*64 + nt*8 + (lane & 3)*2;
          float v0 = acc[mt][nt][half*2 + 0];
          float v1 = acc[mt][nt][half*2 + 1];
          __half2 hv;
          hv.x = __float2half_rn(gelu_f(v0));
          hv.y = __float2half_rn(gelu_f(v1));
          *(__half2*)(Hh + (size_t)drow * N + col) = hv;
        }
      }
    }
  }
}

// ==== MoE DOWN: dense contiguous A (slot order), M=256 per block (2 subtiles), scatter-add ====
__global__ __launch_bounds__(256, 2)
void gemm_moe_down(const __half* __restrict__ Hh, const __half* __restrict__ Bhg,
                   float* __restrict__ out, int N, int K,
                   const int* __restrict__ bucket, const int* __restrict__ counts,
                   const float* __restrict__ pairw)
{
  extern __shared__ char dynsm[];
  int tid = threadIdx.x, wid = tid >> 5, lane = tid & 31;
  int e = blockIdx.z;
  int mcount = counts[e];
  int mbase = blockIdx.y * 256;
  if (mbase >= mcount) return;
  int offe = 0;
  for (int i = 0; i < NE; i++) offe += (i < e) ? counts[i] : 0;
  int n0 = blockIdx.x * 128;
  const __half* Bexp = Bhg + (size_t)e * K * N;
  uint32_t sbase = smem_u32(dynsm);

  int wm = wid >> 1, wn = wid & 1;
  uint32_t aoff  = (uint32_t)((wm*32 + (lane & 15))*144 + ((lane >> 4) << 4));
  uint32_t btoff = (uint32_t)((lane & 15)*272 + wn*128 + ((lane >> 4) << 4));
  int nkt = K / MBKE;

  #pragma unroll 1
  for (int ms = 0; ms < 2; ms++) {
    int m0 = mbase + ms * 128;
    if (m0 >= mcount) break;
    const __half* Ahg = Hh + (size_t)(offe + m0) * K;   // contiguous rows

    auto load_chunk = [&](int stage, int k0) {
      uint32_t st = sbase + stage * MSTGB;
      #pragma unroll
      for (int i = 0; i < 4; i++) {
        int u = tid + i*256;
        int row = u >> 3, c = u & 7;
        cp16(st + row*144 + c*16, Ahg + (size_t)row * K + k0 + c*8);
      }
      #pragma unroll
      for (int i = 0; i < 4; i++) {
        int u = tid + i*256;
        int row = u >> 4, c = u & 15;
        cp16(st + MAREG + row*272 + c*16, Bexp + (size_t)(k0 + row) * N + n0 + c*8);
      }
      cp_commit();
    };

    float acc[2][8][4];
    #pragma unroll
    for (int i = 0; i < 2; i++)
      #pragma unroll
      for (int j = 0; j < 8; j++)
        #pragma unroll
        for (int q = 0; q < 4; q++) acc[i][j][q] = 0.f;

    auto compute = [&](int stage) {
      uint32_t st = sbase + stage * MSTGB;
      uint32_t bb = st + MAREG;
      #pragma unroll
      for (int ks = 0; ks < 4; ks++) {
        uint32_t ah[2][4];
        ldsm4(ah[0], st + aoff + ks*32);
        ldsm4(ah[1], st + aoff + 16*144 + ks*32);
        #pragma unroll
        for (int g = 0; g < 4; g++) {
          uint32_t bh[4];
          ldsm4t(bh, bb + btoff + ks*16*272 + g*32);
          #pragma unroll
          for (int t = 0; t < 2; t++) {
            #pragma unroll
            for (int mt = 0; mt < 2; mt++)
              mma_f16(acc[mt][g*2 + t], ah[mt], bh + t*2);
          }
        }
      }
    };

    load_chunk(0, 0);
    if (nkt > 1) load_chunk(1, MBKE);
    for (int kt = 0; kt < nkt; kt++) {
      if (kt + 1 < nkt) cp_wait<1>(); else cp_wait<0>();
      __syncthreads();
      if (kt + 2 < nkt) load_chunk((kt + 2) % 3, (kt + 2) * MBKE);
      compute(kt % 3);
    }

    #pragma unroll
    for (int mt = 0; mt < 2; mt++) {
      #pragma unroll
      for (int half = 0; half < 2; half++) {
        int rl = wm*32 + mt*16 + (lane >> 2) + half*8;
        int gmi = m0 + rl;
        if (gmi < mcount) {
          int pr = bucket[e * NPAIR + gmi];
          float w = pairw[pr];
          #pragma unroll
          for (int nt = 0; nt < 8; nt++) {
            int col = n0 + wn*64 + nt*8 + (lane & 3)*2;
            float* cp = out + (size_t)(pr >> 1) * N + col;
            atomicAdd(cp + 0, acc[mt][nt][half*2 + 0] * w);
            atomicAdd(cp + 1, acc[mt][nt][half*2 + 1] * w);
          }
        }
      }
    }
    if (ms == 0) __syncthreads();   // smem reuse barrier before next subtile
  }
}

// ============ Tensor-core flash attention (fp16 split-3, fp32 softmax) ============
__global__ __launch_bounds__(256, 2)
void attn_tc(const __half* __restrict__ qkvh, const __half* __restrict__ qkvl,
             __half* __restrict__ oh, __half* __restrict__ ol) {
  extern __shared__ char dynsm[];
  uint32_t sb = smem_u32(dynsm);
  int tid = threadIdx.x, wid = tid >> 5, lane = tid & 31;
  int qt = blockIdx.x, h = blockIdx.y, b = blockIdx.z;
  int qcol = h*HD, kcol = DIM + h*HD, vcol = 2*DIM + h*HD;
  size_t rowbase = (size_t)b * TSEQ;

  auto loadKV = [&](int kt, int buf) {
    uint32_t kb = sb + AT_KV0 + buf * KVBUF;
    #pragma unroll
    for (int i = 0; i < 2; i++) {
      int u = tid + i*256;
      int r = u >> 3, c = u & 7;
      size_t gk = (rowbase + kt*64 + r) * QKVN;
      uint32_t so = r*AT_ROWB + c*16;
      cp16(kb + so,                qkvh + gk + kcol + c*8);
      cp16(kb + 64*AT_ROWB + so,   qkvl + gk + kcol + c*8);
      cp16(kb + 2*64*AT_ROWB + so, qkvh + gk + vcol + c*8);
      cp16(kb + 3*64*AT_ROWB + so, qkvl + gk + vcol + c*8);
    }
    cp_commit();
  };

  #pragma unroll
  for (int i = 0; i < 4; i++) {
    int u = tid + i*256;
    int r = u >> 3, c = u & 7;
    size_t go = (rowbase + qt*128 + r) * QKVN + qcol + c*8;
    uint32_t so = r*AT_ROWB + c*16;
    cp16(sb + so,         qkvh + go);
    cp16(sb + AT_QL + so, qkvl + go);
  }
  loadKV(0, 0);

  uint32_t aoff = (uint32_t)((wid*16 + (lane & 15))*AT_ROWB + (lane >> 4)*16);
  uint32_t kboff = (uint32_t)(((lane & 7) + ((lane >> 4) << 3))*AT_ROWB + ((lane >> 3) & 1)*16);
  uint32_t voff = (uint32_t)((lane & 15)*AT_ROWB + (lane >> 4)*16);

  float O[8][4];
  #pragma unroll
  for (int i = 0; i < 8; i++)
    #pragma unroll
    for (int j = 0; j < 4; j++) O[i][j] = 0.f;
  float m0 = -1e30f, m1 = -1e30f, l0 = 0.f, l1 = 0.f;

  for (int kt = 0; kt < 16; kt++) {
    cp_wait<0>();
    __syncthreads();
    if (kt < 15) loadKV(kt + 1, (kt + 1) & 1);
    uint32_t kvb = sb + AT_KV0 + (kt & 1) * KVBUF;
    uint32_t KH = kvb, KL = kvb + 64*AT_ROWB, VH = kvb + 2*64*AT_ROWB, VL = kvb + 3*64*AT_ROWB;

    float S[8][4];
    #pragma unroll
    for (int i = 0; i < 8; i++)
      #pragma unroll
      for (int j = 0; j < 4; j++) S[i][j] = 0.f;
    #pragma unroll
    for (int kk = 0; kk < 4; kk++) {
      uint32_t kb = kk*32;
      uint32_t ah[4], al[4];
      ldsm4(ah, sb + aoff + kb);
      ldsm4(al, sb + AT_QL + aoff + kb);
      #pragma unroll
      for (int g = 0; g < 4; g++) {
        uint32_t kh[4], kl[4];
        ldsm4(kh, KH + kboff + g*16*AT_ROWB + kb);
        ldsm4(kl, KL + kboff + g*16*AT_ROWB + kb);
        #pragma unroll
        for (int t = 0; t < 2; t++) {
          float* c = S[g*2 + t];
          mma_f16(c, ah, kl + t*2);
          mma_f16(c, al, kh + t*2);
          mma_f16(c, ah, kh + t*2);
        }
      }
    }

    float mx0 = -1e30f, mx1 = -1e30f;
    #pragma unroll
    for (int nt = 0; nt < 8; nt++) {
      mx0 = fmaxf(mx0, fmaxf(S[nt][0], S[nt][1]));
      mx1 = fmaxf(mx1, fmaxf(S[nt][2], S[nt][3]));
    }
    mx0 = fmaxf(mx0, __shfl_xor_sync(0xffffffffu, mx0, 1));
    mx0 = fmaxf(mx0, __shfl_xor_sync(0xffffffffu, mx0, 2));
    mx1 = fmaxf(mx1, __shfl_xor_sync(0xffffffffu, mx1, 1));
    mx1 = fmaxf(mx1, __shfl_xor_sync(0xffffffffu, mx1, 2));
    float mn0 = fmaxf(m0, mx0), mn1 = fmaxf(m1, mx1);
    float a0 = __expf(m0 - mn0), a1 = __expf(m1 - mn1);
    float s0 = 0.f, s1 = 0.f;
    #pragma unroll
    for (int nt = 0; nt < 8; nt++) {
      S[nt][0] = __expf(S[nt][0] - mn0);
      S[nt][1] = __expf(S[nt][1] - mn0);
      S[nt][2] = __expf(S[nt][2] - mn1);
      S[nt][3] = __expf(S[nt][3] - mn1);
      s0 += S[nt][0] + S[nt][1];
      s1 += S[nt][2] + S[nt][3];
    }
    s0 += __shfl_xor_sync(0xffffffffu, s0, 1);
    s0 += __shfl_xor_sync(0xffffffffu, s0, 2);
    s1 += __shfl_xor_sync(0xffffffffu, s1, 1);
    s1 += __shfl_xor_sync(0xffffffffu, s1, 2);
    l0 = l0*a0 + s0; l1 = l1*a1 + s1;
    m0 = mn0; m1 = mn1;
    #pragma unroll
    for (int nt = 0; nt < 8; nt++) {
      O[nt][0] *= a0; O[nt][1] *= a0;
      O[nt][2] *= a1; O[nt][3] *= a1;
    }

    #pragma unroll
    for (int kk = 0; kk < 4; kk++) {
      uint32_t ph[4], pl[4];
      #pragma unroll
      for (int half = 0; half < 2; half++) {
        float* sp = S[kk*2 + half];
        float h00 = __half2float(__float2half_rn(sp[0]));
        float h01 = __half2float(__float2half_rn(sp[1]));
        float h02 = __half2float(__float2half_rn(sp[2]));
        float h03 = __half2float(__float2half_rn(sp[3]));
        ph[half*2 + 0] = packh2(h00, h01);
        ph[half*2 + 1] = packh2(h02, h03);
        pl[half*2 + 0] = packh2(sp[0] - h00, sp[1] - h01);
        pl[half*2 + 1] = packh2(sp[2] - h02, sp[3] - h03);
      }
      #pragma unroll
      for (int nb = 0; nb < 4; nb++) {
        uint32_t vh[4], vl[4];
        uint32_t va = voff + kk*16*AT_ROWB + nb*32;
        ldsm4t(vh, VH + va);
        ldsm4t(vl, VL + va);
        #pragma unroll
        for (int t = 0; t < 2; t++) {
          float* c = O[nb*2 + t];
          mma_f16(c, ph, vl + t*2);
          mma_f16(c, pl, vh + t*2);
          mma_f16(c, ph, vh + t*2);
        }
      }
    }
  }

  float inv0 = 1.0f / l0, inv1 = 1.0f / l1;
  int r0 = qt*128 + wid*16 + (lane >> 2);
  size_t ob0 = (rowbase + r0) * DIM;
  size_t ob1 = (rowbase + r0 + 8) * DIM;
  #pragma unroll
  for (int nt = 0; nt < 8; nt++) {
    int col = h*HD + nt*8 + (lane & 3)*2;
    float v0 = O[nt][0]*inv0, v1 = O[nt][1]*inv0;
    float v2 = O[nt][2]*inv1, v3 = O[nt][3]*inv1;
    float h0 = __half2float(__float2half_rn(v0)), h1 = __half2float(__float2half_rn(v1));
    float h2 = __half2float(__float2half_rn(v2)), h3 = __half2float(__float2half_rn(v3));
    *(uint32_t*)(oh + ob0 + col) = packh2(v0, v1);
    *(uint32_t*)(ol + ob0 + col) = packh2(v0 - h0, v1 - h1);
    *(uint32_t*)(oh + ob1 + col) = packh2(v2, v3);
    *(uint32_t*)(ol + ob1 + col) = packh2(v2 - h2, v3 - h3);
  }
}

// --------- ONE weight-prep kernel ---------
__global__ void convert_all(const float* __restrict__ W1, __half* __restrict__ W1h,
                            const float* __restrict__ W2, __half* __restrict__ W2h,
                            const float* __restrict__ Wq, __half* __restrict__ Wqh,
                            __half* __restrict__ Wql,
                            const float* __restrict__ Wp, __half* __restrict__ Wph,
                            __half* __restrict__ Wpl, int* __restrict__ count) {
  int y = blockIdx.y;
  if (y == 0 && blockIdx.x == 0 && threadIdx.x < NE) count[threadIdx.x] = 0;
  const float* in; __half* oh; __half* ol = nullptr; int n;
  if (y == 0)      { in = W1; oh = W1h; n = NE*DIM*FFD; }
  else if (y == 1) { in = W2; oh = W2h; n = NE*DIM*FFD; }
  else if (y == 2) { in = Wq; oh = Wqh; ol = Wql; n = DIM*QKVN; }
  else             { in = Wp; oh = Wph; ol = Wpl; n = DIM*DIM; }
  int i = (blockIdx.x * 256 + threadIdx.x) * 8;
  if (i >= n) return;
  float4 a = *(const float4*)(in + i);
  float4 b = *(const float4*)(in + i + 4);
  uint4 o;
  o.x = packh2(a.x, a.y);
  o.y = packh2(a.z, a.w);
  o.z = packh2(b.x, b.y);
  o.w = packh2(b.z, b.w);
  *(uint4*)(oh + i) = o;
  if (ol) {
    float hx0 = __half2float(__float2half_rn(a.x)), hx1 = __half2float(__float2half_rn(a.y));
    float hx2 = __half2float(__float2half_rn(a.z)), hx3 = __half2float(__float2half_rn(a.w));
    float hy0 = __half2float(__float2half_rn(b.x)), hy1 = __half2float(__float2half_rn(b.y));
    float hy2 = __half2float(__float2half_rn(b.z)), hy3 = __half2float(__float2half_rn(b.w));
    uint4 l;
    l.x = packh2(a.x - hx0, a.y - hx1);
    l.y = packh2(a.z - hx2, a.w - hx3);
    l.z = packh2(b.x - hy0, b.y - hy1);
    l.w = packh2(b.z - hy2, b.w - hy3);
    *(uint4*)(ol + i) = l;
  }
}

// ---------------- LayerNorm (LN1: fp16 hi/lo) ----------------
__global__ void ln_kernel(const float* __restrict__ in, const float* __restrict__ gam,
                          const float* __restrict__ bet,
                          __half* __restrict__ oh, __half* __restrict__ ol) {
  __shared__ float red[256];
  int row = blockIdx.x, tid = threadIdx.x;
  const float* x = in + (size_t)row * DIM;
  float v0 = x[tid], v1 = x[tid+256], v2 = x[tid+512];
  red[tid] = v0+v1+v2; __syncthreads();
  for (int o=128;o;o>>=1){ if (tid<o) red[tid]+=red[tid+o]; __syncthreads(); }
  float mean = red[0] * (1.0f/DIM);
  __syncthreads();
  float d0=v0-mean, d1=v1-mean, d2=v2-mean;
  red[tid] = d0*d0+d1*d1+d2*d2; __syncthreads();
  for (int o=128;o;o>>=1){ if (tid<o) red[tid]+=red[tid+o]; __syncthreads(); }
  float r = rsqrtf(red[0]*(1.0f/DIM) + 1e-5f);
  size_t base = (size_t)row * DIM;
  #pragma unroll
  for (int j = 0; j < 3; j++) {
    int c = tid + j*256;
    float d = (j==0) ? d0 : (j==1) ? d1 : d2;
    float v = d*r*gam[c] + bet[c];
    __half h = __float2half_rn(v);
    oh[base + c] = h;
    ol[base + c] = __float2half_rn(v - __half2float(h));
  }
}

// ---------- Fused LN2 + router ----------
__global__ void ln2_router(const float* __restrict__ in, const float* __restrict__ gam,
                           const float* __restrict__ bet, const float* __restrict__ Wr,
                           __half* __restrict__ oh, float* __restrict__ ocopy,
                           int* __restrict__ bucket, float* __restrict__ pairw,
                           int* __restrict__ count) {
  __shared__ float red[256];
  __shared__ float part[8][NE];
  int row = blockIdx.x, tid = threadIdx.x;
  int wid = tid >> 5, lane = tid & 31;
  const float* x = in + (size_t)row * DIM;
  float v0 = x[tid], v1 = x[tid+256], v2 = x[tid+512];
  red[tid] = v0+v1+v2; __syncthreads();
  for (int o=128;o;o>>=1){ if (tid<o) red[tid]+=red[tid+o]; __syncthreads(); }
  float mean = red[0] * (1.0f/DIM);
  __syncthreads();
  float d0=v0-mean, d1=v1-mean, d2=v2-mean;
  red[tid] = d0*d0+d1*d1+d2*d2; __syncthreads();
  for (int o=128;o;o>>=1){ if (tid<o) red[tid]+=red[tid+o]; __syncthreads(); }
  float r = rsqrtf(red[0]*(1.0f/DIM) + 1e-5f);
  size_t base = (size_t)row * DIM;
  float ln[3];
  #pragma unroll
  for (int j = 0; j < 3; j++) {
    int c = tid + j*256;
    float raw = (j==0) ? v0 : (j==1) ? v1 : v2;
    float d = (j==0) ? d0 : (j==1) ? d1 : d2;
    float v = d*r*gam[c] + bet[c];
    ln[j] = v;
    ocopy[base + c] = raw;
    oh[base + c] = __float2half_rn(v);
  }
  float lg[NE];
  #pragma unroll
  for (int e = 0; e < NE; e++) {
    lg[e] = ln[0]*Wr[tid*NE + e] + ln[1]*Wr[(tid+256)*NE + e] + ln[2]*Wr[(tid+512)*NE + e];
    #pragma unroll
    for (int off = 16; off; off >>= 1) lg[e] += __shfl_xor_sync(0xffffffffu, lg[e], off);
  }
  if (lane == 0) {
    #pragma unroll
    for (int e = 0; e < NE; e++) part[wid][e] = lg[e];
  }
  __syncthreads();
  if (tid == 0) {
    float L[NE];
    #pragma unroll
    for (int e = 0; e < NE; e++) {
      float s = 0.f;
      #pragma unroll
      for (int w = 0; w < 8; w++) s += part[w][e];
      L[e] = s;
    }
    int i0 = 0;
    #pragma unroll
    for (int e = 1; e < NE; e++) if (L[e] > L[i0]) i0 = e;
    int i1 = (i0 == 0) ? 1 : 0;
    #pragma unroll
    for (int e = 0; e < NE; e++) { if (e == i0) continue; if (L[e] > L[i1]) i1 = e; }
    float w0 = 1.f / (1.f + expf(L[i1] - L[i0]));
    float w1 = 1.f - w0;
    int p0 = row*2, p1 = row*2 + 1;
    pairw[p0] = w0; pairw[p1] = w1;
    int q0 = atomicAdd(&count[i0], 1); bucket[i0*NPAIR + q0] = p0;
    int q1 = atomicAdd(&count[i1], 1); bucket[i1*NPAIR + q1] = p1;
  }
}

extern "C" void kernel_launch(void* const* d_in, const int* in_sizes, int n_in,
                              void* d_out, int out_size) {
  const float* x       = (const float*)d_in[0];
  const float* Wqkv    = (const float*)d_in[1];
  const float* Wproj   = (const float*)d_in[2];
  const float* Wrouter = (const float*)d_in[3];
  const float* W1      = (const float*)d_in[4];
  const float* W2      = (const float*)d_in[5];
  const float* ln1g    = (const float*)d_in[6];
  const float* ln1b    = (const float*)d_in[7];
  const float* ln2g    = (const float*)d_in[8];
  const float* ln2b    = (const float*)d_in[9];
  float* out = (float*)d_out;

  Scratch* s = nullptr;
  cudaGetSymbolAddress((void**)&s, g_s);

  cudaFuncSetAttribute(attn_tc, cudaFuncAttributeMaxDynamicSharedMemorySize, AT_SMEM);
  cudaFuncSetAttribute(gemm_split<0>, cudaFuncAttributeMaxDynamicSharedMemorySize, GSMEM_SPLIT);
  cudaFuncSetAttribute(gemm_split<1>, cudaFuncAttributeMaxDynamicSharedMemorySize, GSMEM_SPLIT);
  cudaFuncSetAttribute(gemm_moe_up, cudaFuncAttributeMaxDynamicSharedMemorySize, GSMEM_MOE);
  cudaFuncSetAttribute(gemm_moe_down, cudaFuncAttributeMaxDynamicSharedMemorySize, GSMEM_MOE);

  convert_all<<<dim3((NE*DIM*FFD)/2048, 4), 256>>>(
      W1, s->W1h, W2, s->W2h, Wqkv, s->Wqkvh, s->Wqkvl, Wproj, s->Wprojh, s->Wprojl, s->count);

  ln_kernel<<<NTOK, 256>>>(x, ln1g, ln1b, s->xln1h, s->xln1l);
  gemm_split<0><<<dim3(QKVN/128, NTOK/128, 1), 256, GSMEM_SPLIT>>>(
      s->xln1h, s->xln1l, s->Wqkvh, s->Wqkvl, nullptr, s->qkvh, s->qkvl,
      NTOK, QKVN, DIM, nullptr);
  attn_tc<<<dim3(TSEQ/128, NH, NB), 256, AT_SMEM>>>(s->qkvh, s->qkvl, s->attnh, s->attnl);
  gemm_split<1><<<dim3(DIM/128, NTOK/128, 1), 256, GSMEM_SPLIT>>>(
      s->attnh, s->attnl, s->Wprojh, s->Wprojl, s->x1, nullptr, nullptr,
      NTOK, DIM, DIM, x);

  ln2_router<<<NTOK, 256>>>(s->x1, ln2g, ln2b, Wrouter, s->xln2h, out,
                            s->bucket, s->pairw, s->count);
  gemm_moe_up<<<dim3(FFD/128, NPAIR/128, NE), 256, GSMEM_MOE>>>(
      s->xln2h, s->W1h, s->Hh, FFD, DIM, s->bucket, s->count);
  gemm_moe_down<<<dim3(DIM/128, NPAIR/256, NE), 256, GSMEM_MOE>>>(
      s->Hh, s->W2h, out, DIM, FFD, s->bucket, s->count, s->pairw);
}

// round 16
// speedup vs baseline: 1.0650x; 1.0650x over previous
#include <cuda_runtime.h>
#include <cuda_fp16.h>
#include <math.h>
#include <stdint.h>

#define NTOK 4096
#define DIM 768
#define QKVN (3*DIM)
#define FFD 3072
#define NE 8
#define NPAIR (NTOK*2)
#define TSEQ 1024
#define NB 4
#define NH 12
#define HD 64

// split GEMM: swizzled 64B rows, 3 stages x (Ah,Al,Bh,Bl), BK=32
#define SBKE 32
#define SAREG 8192
#define SSTGB (4*SAREG)
#define GSMEM_SPLIT (3*SSTGB)           // 98304

// MoE GEMM: BK=64. A 128x144B + B-trans 64x272B, 3 stages
#define MBKE 64
#define MAREG (128*144)                 // 18432
#define MBREG (64*272)                  // 17408
#define MSTGB (MAREG + MBREG)           // 35840
#define GSMEM_MOE (3*MSTGB)             // 107520

// attention: Q 128x64 hi/lo + double-buffered KV
#define AT_ROWB 144
#define AT_QL   (128*AT_ROWB)
#define AT_KV0  (2*128*AT_ROWB)
#define KVBUF   (4*64*AT_ROWB)
#define AT_SMEM (AT_KV0 + 2*KVBUF)      // 110592

struct Scratch {
  float x1[(size_t)NTOK*DIM];
  __half qkvh[(size_t)NTOK*QKVN], qkvl[(size_t)NTOK*QKVN];
  __half xln1h[(size_t)NTOK*DIM], xln1l[(size_t)NTOK*DIM];
  __half attnh[(size_t)NTOK*DIM], attnl[(size_t)NTOK*DIM];
  __half xln2h[(size_t)NTOK*DIM];
  __half Hh[(size_t)NPAIR*FFD];
  __half Wqkvth[(size_t)QKVN*DIM], Wqkvtl[(size_t)QKVN*DIM];
  __half Wprojth[(size_t)DIM*DIM], Wprojtl[(size_t)DIM*DIM];
  __half W1h[(size_t)NE*DIM*FFD];       // native [e][k][n]
  __half W2h[(size_t)NE*FFD*DIM];       // native [e][k][n]
  float pairw[NPAIR];
  int bucket[NE*NPAIR];
  int count[NE];
};
__device__ Scratch g_s;

__device__ __forceinline__ float gelu_f(float v) {
  return 0.5f * v * (1.0f + erff(v * 0.70710678118654752f));
}
__device__ __forceinline__ uint32_t smem_u32(const void* p) {
  uint32_t a;
  asm("{ .reg .u64 t; cvta.to.shared.u64 t, %1; cvt.u32.u64 %0, t; }" : "=r"(a) : "l"(p));
  return a;
}
__device__ __forceinline__ void cp16(uint32_t dst, const void* src) {
  asm volatile("cp.async.cg.shared.global [%0], [%1], 16;\n" :: "r"(dst), "l"(src));
}
__device__ __forceinline__ void cp_commit() { asm volatile("cp.async.commit_group;\n"); }
template<int N> __device__ __forceinline__ void cp_wait() {
  asm volatile("cp.async.wait_group %0;\n" :: "n"(N));
}
__device__ __forceinline__ void ldsm4(uint32_t* r, uint32_t addr) {
  asm volatile("ldmatrix.sync.aligned.m8n8.x4.shared.b16 {%0,%1,%2,%3}, [%4];"
    : "=r"(r[0]), "=r"(r[1]), "=r"(r[2]), "=r"(r[3]) : "r"(addr));
}
__device__ __forceinline__ void ldsm4t(uint32_t* r, uint32_t addr) {
  asm volatile("ldmatrix.sync.aligned.m8n8.x4.trans.shared.b16 {%0,%1,%2,%3}, [%4];"
    : "=r"(r[0]), "=r"(r[1]), "=r"(r[2]), "=r"(r[3]) : "r"(addr));
}
__device__ __forceinline__ void mma_f16(float* c, const uint32_t* a, const uint32_t* b) {
  asm volatile(
    "mma.sync.aligned.m16n8k16.row.col.f32.f16.f16.f32 "
    "{%0,%1,%2,%3},{%4,%5,%6,%7},{%8,%9},{%0,%1,%2,%3};\n"
    : "+f"(c[0]), "+f"(c[1]), "+f"(c[2]), "+f"(c[3])
    : "r"(a[0]), "r"(a[1]), "r"(a[2]), "r"(a[3]), "r"(b[0]), "r"(b[1]));
}
__device__ __forceinline__ uint32_t packh2(float x, float y) {
  __half2 h; h.x = __float2half_rn(x); h.y = __float2half_rn(y);
  return *(uint32_t*)&h;
}
__device__ __forceinline__ uint32_t swz(int row, int c) {
  return (uint32_t)(row*64 + ((c ^ ((row >> 1) & 3)) << 4));
}

// =============== split-3 fp16 GEMM (router-safe path), swizzled, 3-stage ===============
// MODE 0: qkv = A@B -> fp16 hi/lo (Q scaled 0.125)   MODE 1: x1 = A@B + resid -> f32
template<int MODE>
__global__ __launch_bounds__(256, 2)
void gemm_split(const __half* __restrict__ Ahg, const __half* __restrict__ Alg,
                const __half* __restrict__ Bhg, const __half* __restrict__ Blg,
                float* __restrict__ Cf, __half* __restrict__ Chalf, __half* __restrict__ Chalf2,
                int M, int N, int K, const float* __restrict__ resid)
{
  extern __shared__ char dynsm[];
  int tid = threadIdx.x, wid = tid >> 5, lane = tid & 31;
  int m0 = blockIdx.y * 128;
  int n0 = blockIdx.x * 128;
  uint32_t sbase = smem_u32(dynsm);

  auto load_chunk = [&](int stage, int k0) {
    uint32_t st = sbase + stage * SSTGB;
    #pragma unroll
    for (int i = 0; i < 2; i++) {
      int u = tid + i*256;
      int row = u >> 2, c = u & 3;
      uint32_t so = swz(row, c);
      size_t go = (size_t)(m0 + row) * K + k0 + c*8;
      cp16(st + so,         Ahg + go);
      cp16(st + SAREG + so, Alg + go);
    }
    #pragma unroll
    for (int i = 0; i < 2; i++) {
      int u = tid + i*256;
      int row = u >> 2, c = u & 3;
      uint32_t so = swz(row, c);
      size_t go = (size_t)(n0 + row) * K + k0 + c*8;
      cp16(st + 2*SAREG + so, Bhg + go);
      cp16(st + 3*SAREG + so, Blg + go);
    }
    cp_commit();
  };

  int wm = wid >> 1, wn = wid & 1;
  int arow = wm*32 + (lane & 15);
  int acs  = (lane >> 4);
  int brow = wn*64 + (lane & 7) + ((lane >> 4) << 3);
  int bcs  = (lane >> 3) & 1;

  float acc[2][8][4];
  #pragma unroll
  for (int i = 0; i < 2; i++)
    #pragma unroll
    for (int j = 0; j < 8; j++)
      #pragma unroll
      for (int q = 0; q < 4; q++) acc[i][j][q] = 0.f;

  auto compute = [&](int stage) {
    uint32_t st = sbase + stage * SSTGB;
    #pragma unroll
    for (int ks = 0; ks < 2; ks++) {
      uint32_t ah[2][4], al[2][4];
      ldsm4(ah[0], st +         swz(arow,      acs + ks*2));
      ldsm4(ah[1], st +         swz(arow + 16, acs + ks*2));
      ldsm4(al[0], st + SAREG + swz(arow,      acs + ks*2));
      ldsm4(al[1], st + SAREG + swz(arow + 16, acs + ks*2));
      #pragma unroll
      for (int g = 0; g < 4; g++) {
        uint32_t bh[4], bl[4];
        ldsm4(bh, st + 2*SAREG + swz(brow + g*16, bcs + ks*2));
        ldsm4(bl, st + 3*SAREG + swz(brow + g*16, bcs + ks*2));
        #pragma unroll
        for (int t = 0; t < 2; t++) {
          #pragma unroll
          for (int mt = 0; mt < 2; mt++) {
            float* c = acc[mt][g*2 + t];
            mma_f16(c, ah[mt], bl + t*2);
            mma_f16(c, al[mt], bh + t*2);
            mma_f16(c, ah[mt], bh + t*2);
          }
        }
      }
    }
  };

  int nkt = K / SBKE;
  load_chunk(0, 0);
  if (nkt > 1) load_chunk(1, SBKE);
  for (int kt = 0; kt < nkt; kt++) {
    if (kt + 1 < nkt) cp_wait<1>(); else cp_wait<0>();
    __syncthreads();
    if (kt + 2 < nkt) load_chunk((kt + 2) % 3, (kt + 2) * SBKE);
    compute(kt % 3);
  }

  #pragma unroll
  for (int mt = 0; mt < 2; mt++) {
    #pragma unroll
    for (int half = 0; half < 2; half++) {
      int gmi = m0 + wm*32 + mt*16 + (lane >> 2) + half*8;
      #pragma unroll
      for (int nt = 0; nt < 8; nt++) {
        int col = n0 + wn*64 + nt*8 + (lane & 3)*2;
        float v0 = acc[mt][nt][half*2 + 0];
        float v1 = acc[mt][nt][half*2 + 1];
        if constexpr (MODE == 0) {
          float sc = (col < DIM) ? 0.125f : 1.0f;
          v0 *= sc; v1 *= sc;
          __half h0 = __float2half_rn(v0), h1 = __float2half_rn(v1);
          __half2 hv; hv.x = h0; hv.y = h1;
          __half2 lv;
          lv.x = __float2half_rn(v0 - __half2float(h0));
          lv.y = __float2half_rn(v1 - __half2float(h1));
          *(__half2*)(Chalf + (size_t)gmi * N + col) = hv;
          *(__half2*)(Chalf2 + (size_t)gmi * N + col) = lv;
        } else {
          const float* rp = resid + (size_t)gmi * N + col;
          *(float2*)(Cf + (size_t)gmi * N + col) = make_float2(v0 + rp[0], v1 + rp[1]);
        }
      }
    }
  }
}

// =============== MoE fp16 GEMM: BK=64, native [k][n] weights via ldsm4t, 3-stage ===============
// MODE 2: H[pair] = gelu(A[tok]@W1[e]) -> fp16    MODE 3: out[tok] += w*(H[pair]@W2[e])
template<int MODE>
__global__ __launch_bounds__(256, 2)
void gemm_moe(const __half* __restrict__ Ahg, const __half* __restrict__ Bhg,
              float* __restrict__ Cf, __half* __restrict__ Chalf,
              int N, int K,
              const int* __restrict__ bucket, const int* __restrict__ counts,
              const float* __restrict__ pairw)
{
  extern __shared__ char dynsm[];
  __shared__ int sPair[128];
  int tid = threadIdx.x, wid = tid >> 5, lane = tid & 31;
  int e = blockIdx.z;
  int mcount = counts[e];
  int m0 = blockIdx.y * 128;
  if (m0 >= mcount) return;
  int n0 = blockIdx.x * 128;
  Bhg += (size_t)e * K * N;
  if (tid < 128) {
    int gm = m0 + tid;
    sPair[tid] = bucket[e * NPAIR + (gm < mcount ? gm : mcount - 1)];
  }
  __syncthreads();

  uint32_t sbase = smem_u32(dynsm);

  int arow4[4];
  #pragma unroll
  for (int i = 0; i < 4; i++) {
    int row = (tid + i*256) >> 3;
    arow4[i] = (MODE == 2) ? (sPair[row] >> 1) : sPair[row];
  }

  auto load_chunk = [&](int stage, int k0) {
    uint32_t st = sbase + stage * MSTGB;
    #pragma unroll
    for (int i = 0; i < 4; i++) {
      int u = tid + i*256;
      int row = u >> 3, c = u & 7;
      cp16(st + row*144 + c*16, Ahg + (size_t)arow4[i] * K + k0 + c*8);
    }
    #pragma unroll
    for (int i = 0; i < 4; i++) {
      int u = tid + i*256;
      int row = u >> 4, c = u & 15;          // 64 k-rows x 256B
      cp16(st + MAREG + row*272 + c*16, Bhg + (size_t)(k0 + row) * N + n0 + c*8);
    }
    cp_commit();
  };

  int wm = wid >> 1, wn = wid & 1;
  uint32_t aoff  = (uint32_t)((wm*32 + (lane & 15))*144 + ((lane >> 4) << 4));
  uint32_t btoff = (uint32_t)((lane & 15)*272 + wn*128 + ((lane >> 4) << 4));

  float acc[2][8][4];
  #pragma unroll
  for (int i = 0; i < 2; i++)
    #pragma unroll
    for (int j = 0; j < 8; j++)
      #pragma unroll
      for (int q = 0; q < 4; q++) acc[i][j][q] = 0.f;

  auto compute = [&](int stage) {
    uint32_t st = sbase + stage * MSTGB;
    uint32_t bb = st + MAREG;
    #pragma unroll
    for (int ks = 0; ks < 4; ks++) {
      uint32_t ah[2][4];
      ldsm4(ah[0], st + aoff + ks*32);
      ldsm4(ah[1], st + aoff + 16*144 + ks*32);
      #pragma unroll
      for (int g = 0; g < 4; g++) {
        uint32_t bh[4];
        ldsm4t(bh, bb + btoff + ks*16*272 + g*32);
        #pragma unroll
        for (int t = 0; t < 2; t++) {
          #pragma unroll
          for (int mt = 0; mt < 2; mt++)
            mma_f16(acc[mt][g*2 + t], ah[mt], bh + t*2);
        }
      }
    }
  };

  int nkt = K / MBKE;
  load_chunk(0, 0);
  if (nkt > 1) load_chunk(1, MBKE);
  for (int kt = 0; kt < nkt; kt++) {
    if (kt + 1 < nkt) cp_wait<1>(); else cp_wait<0>();
    __syncthreads();
    if (kt + 2 < nkt) load_chunk((kt + 2) % 3, (kt + 2) * MBKE);
    compute(kt % 3);
  }

  #pragma unroll
  for (int mt = 0; mt < 2; mt++) {
    #pragma unroll
    for (int half = 0; half < 2; half++) {
      int rl = wm*32 + mt*16 + (lane >> 2) + half*8;
      int gmi = m0 + rl;
      if (gmi < mcount) {
        int pr = sPair[rl];
        #pragma unroll
        for (int nt = 0; nt < 8; nt++) {
          int col = n0 + wn*64 + nt*8 + (lane & 3)*2;
          float v0 = acc[mt][nt][half*2 + 0];
          float v1 = acc[mt][nt][half*2 + 1];
          if constexpr (MODE == 2) {
            __half2 hv;
            hv.x = __float2half_rn(gelu_f(v0));
            hv.y = __float2half_rn(gelu_f(v1));
            *(__half2*)(Chalf + (size_t)pr * N + col) = hv;
          } else {
            float w = pairw[pr];
            float* cp = Cf + (size_t)(pr >> 1) * N + col;
            atomicAdd(cp + 0, v0 * w);
            atomicAdd(cp + 1, v1 * w);
          }
        }
      }
    }
  }
}

// ============ Tensor-core flash attention (fp16 split-3, fp32 softmax) ============
__global__ __launch_bounds__(256, 2)
void attn_tc(const __half* __restrict__ qkvh, const __half* __restrict__ qkvl,
             __half* __restrict__ oh, __half* __restrict__ ol) {
  extern __shared__ char dynsm[];
  uint32_t sb = smem_u32(dynsm);
  int tid = threadIdx.x, wid = tid >> 5, lane = tid & 31;
  int qt = blockIdx.x, h = blockIdx.y, b = blockIdx.z;
  int qcol = h*HD, kcol = DIM + h*HD, vcol = 2*DIM + h*HD;
  size_t rowbase = (size_t)b * TSEQ;

  auto loadKV = [&](int kt, int buf) {
    uint32_t kb = sb + AT_KV0 + buf * KVBUF;
    #pragma unroll
    for (int i = 0; i < 2; i++) {
      int u = tid + i*256;
      int r = u >> 3, c = u & 7;
      size_t gk = (rowbase + kt*64 + r) * QKVN;
      uint32_t so = r*AT_ROWB + c*16;
      cp16(kb + so,                qkvh + gk + kcol + c*8);
      cp16(kb + 64*AT_ROWB + so,   qkvl + gk + kcol + c*8);
      cp16(kb + 2*64*AT_ROWB + so, qkvh + gk + vcol + c*8);
      cp16(kb + 3*64*AT_ROWB + so, qkvl + gk + vcol + c*8);
    }
    cp_commit();
  };

  #pragma unroll
  for (int i = 0; i < 4; i++) {
    int u = tid + i*256;
    int r = u >> 3, c = u & 7;
    size_t go = (rowbase + qt*128 + r) * QKVN + qcol + c*8;
    uint32_t so = r*AT_ROWB + c*16;
    cp16(sb + so,         qkvh + go);
    cp16(sb + AT_QL + so, qkvl + go);
  }
  loadKV(0, 0);

  uint32_t aoff = (uint32_t)((wid*16 + (lane & 15))*AT_ROWB + (lane >> 4)*16);
  uint32_t kboff = (uint32_t)(((lane & 7) + ((lane >> 4) << 3))*AT_ROWB + ((lane >> 3) & 1)*16);
  uint32_t voff = (uint32_t)((lane & 15)*AT_ROWB + (lane >> 4)*16);

  float O[8][4];
  #pragma unroll
  for (int i = 0; i < 8; i++)
    #pragma unroll
    for (int j = 0; j < 4; j++) O[i][j] = 0.f;
  float m0 = -1e30f, m1 = -1e30f, l0 = 0.f, l1 = 0.f;

  for (int kt = 0; kt < 16; kt++) {
    cp_wait<0>();
    __syncthreads();
    if (kt < 15) loadKV(kt + 1, (kt + 1) & 1);
    uint32_t kvb = sb + AT_KV0 + (kt & 1) * KVBUF;
    uint32_t KH = kvb, KL = kvb + 64*AT_ROWB, VH = kvb + 2*64*AT_ROWB, VL = kvb + 3*64*AT_ROWB;

    float S[8][4];
    #pragma unroll
    for (int i = 0; i < 8; i++)
      #pragma unroll
      for (int j = 0; j < 4; j++) S[i][j] = 0.f;
    #pragma unroll
    for (int kk = 0; kk < 4; kk++) {
      uint32_t kb = kk*32;
      uint32_t ah[4], al[4];
      ldsm4(ah, sb + aoff + kb);
      ldsm4(al, sb + AT_QL + aoff + kb);
      #pragma unroll
      for (int g = 0; g < 4; g++) {
        uint32_t kh[4], kl[4];
        ldsm4(kh, KH + kboff + g*16*AT_ROWB + kb);
        ldsm4(kl, KL + kboff + g*16*AT_ROWB + kb);
        #pragma unroll
        for (int t = 0; t < 2; t++) {
          float* c = S[g*2 + t];
          mma_f16(c, ah, kl + t*2);
          mma_f16(c, al, kh + t*2);
          mma_f16(c, ah, kh + t*2);
        }
      }
    }

    float mx0 = -1e30f, mx1 = -1e30f;
    #pragma unroll
    for (int nt = 0; nt < 8; nt++) {
      mx0 = fmaxf(mx0, fmaxf(S[nt][0], S[nt][1]));
      mx1 = fmaxf(mx1, fmaxf(S[nt][2], S[nt][3]));
    }
    mx0 = fmaxf(mx0, __shfl_xor_sync(0xffffffffu, mx0, 1));
    mx0 = fmaxf(mx0, __shfl_xor_sync(0xffffffffu, mx0, 2));
    mx1 = fmaxf(mx1, __shfl_xor_sync(0xffffffffu, mx1, 1));
    mx1 = fmaxf(mx1, __shfl_xor_sync(0xffffffffu, mx1, 2));
    float mn0 = fmaxf(m0, mx0), mn1 = fmaxf(m1, mx1);
    float a0 = __expf(m0 - mn0), a1 = __expf(m1 - mn1);
    float s0 = 0.f, s1 = 0.f;
    #pragma unroll
    for (int nt = 0; nt < 8; nt++) {
      S[nt][0] = __expf(S[nt][0] - mn0);
      S[nt][1] = __expf(S[nt][1] - mn0);
      S[nt][2] = __expf(S[nt][2] - mn1);
      S[nt][3] = __expf(S[nt][3] - mn1);
      s0 += S[nt][0] + S[nt][1];
      s1 += S[nt][2] + S[nt][3];
    }
    s0 += __shfl_xor_sync(0xffffffffu, s0, 1);
    s0 += __shfl_xor_sync(0xffffffffu, s0, 2);
    s1 += __shfl_xor_sync(0xffffffffu, s1, 1);
    s1 += __shfl_xor_sync(0xffffffffu, s1, 2);
    l0 = l0*a0 + s0; l1 = l1*a1 + s1;
    m0 = mn0; m1 = mn1;
    #pragma unroll
    for (int nt = 0; nt < 8; nt++) {
      O[nt][0] *= a0; O[nt][1] *= a0;
      O[nt][2] *= a1; O[nt][3] *= a1;
    }

    #pragma unroll
    for (int kk = 0; kk < 4; kk++) {
      uint32_t ph[4], pl[4];
      #pragma unroll
      for (int half = 0; half < 2; half++) {
        float* sp = S[kk*2 + half];
        float h00 = __half2float(__float2half_rn(sp[0]));
        float h01 = __half2float(__float2half_rn(sp[1]));
        float h02 = __half2float(__float2half_rn(sp[2]));
        float h03 = __half2float(__float2half_rn(sp[3]));
        ph[half*2 + 0] = packh2(h00, h01);
        ph[half*2 + 1] = packh2(h02, h03);
        pl[half*2 + 0] = packh2(sp[0] - h00, sp[1] - h01);
        pl[half*2 + 1] = packh2(sp[2] - h02, sp[3] - h03);
      }
      #pragma unroll
      for (int nb = 0; nb < 4; nb++) {
        uint32_t vh[4], vl[4];
        uint32_t va = voff + kk*16*AT_ROWB + nb*32;
        ldsm4t(vh, VH + va);
        ldsm4t(vl, VL + va);
        #pragma unroll
        for (int t = 0; t < 2; t++) {
          float* c = O[nb*2 + t];
          mma_f16(c, ph, vl + t*2);
          mma_f16(c, pl, vh + t*2);
          mma_f16(c, ph, vh + t*2);
        }
      }
    }
  }

  float inv0 = 1.0f / l0, inv1 = 1.0f / l1;
  int r0 = qt*128 + wid*16 + (lane >> 2);
  size_t ob0 = (rowbase + r0) * DIM;
  size_t ob1 = (rowbase + r0 + 8) * DIM;
  #pragma unroll
  for (int nt = 0; nt < 8; nt++) {
    int col = h*HD + nt*8 + (lane & 3)*2;
    float v0 = O[nt][0]*inv0, v1 = O[nt][1]*inv0;
    float v2 = O[nt][2]*inv1, v3 = O[nt][3]*inv1;
    float h0 = __half2float(__float2half_rn(v0)), h1 = __half2float(__float2half_rn(v1));
    float h2 = __half2float(__float2half_rn(v2)), h3 = __half2float(__float2half_rn(v3));
    *(uint32_t*)(oh + ob0 + col) = packh2(v0, v1);
    *(uint32_t*)(ol + ob0 + col) = packh2(v0 - h0, v1 - h1);
    *(uint32_t*)(oh + ob1 + col) = packh2(v2, v3);
    *(uint32_t*)(ol + ob1 + col) = packh2(v2 - h2, v3 - h3);
  }
}

// --------- transpose + fp16 split (Wqkv z=0, Wproj z=1 merged) ---------
__global__ void transpose_split2(const float* __restrict__ inQ, __half* __restrict__ ohQ,
                                 __half* __restrict__ olQ,
                                 const float* __restrict__ inP, __half* __restrict__ ohP,
                                 __half* __restrict__ olP) {
  __shared__ float t[32][33];
  int z = blockIdx.z;
  const float* in = z ? inP : inQ;
  __half* oh = z ? ohP : ohQ;
  __half* ol = z ? olP : olQ;
  int C = z ? DIM : QKVN;
  int R = DIM;
  if (z && blockIdx.x >= DIM/32) return;
  int c0 = blockIdx.x * 32, r0 = blockIdx.y * 32;
  int tx = threadIdx.x, ty = threadIdx.y;
  #pragma unroll
  for (int i = 0; i < 32; i += 8)
    t[ty + i][tx] = in[(size_t)(r0 + ty + i) * C + c0 + tx];
  __syncthreads();
  int txl = tx & 15, txh = tx >> 4;
  #pragma unroll
  for (int i = 0; i < 32; i += 16) {
    int orow = ty*2 + txh + i;
    float v0 = t[2*txl][orow], v1 = t[2*txl + 1][orow];
    size_t o = (size_t)(c0 + orow) * R + r0 + 2*txl;
    __half h0 = __float2half_rn(v0), h1 = __float2half_rn(v1);
    __half2 hv; hv.x = h0; hv.y = h1;
    *(__half2*)(oh + o) = hv;
    __half2 lv;
    lv.x = __float2half_rn(v0 - __half2float(h0));
    lv.y = __float2half_rn(v1 - __half2float(h1));
    *(__half2*)(ol + o) = lv;
  }
}

// --------- merged f32 -> fp16 convert for W1+W2 (+ count zeroing) ---------
__global__ void convert_h2(const float* __restrict__ in1, __half* __restrict__ out1,
                           const float* __restrict__ in2, __half* __restrict__ out2,
                           int n, int* __restrict__ count) {
  if (blockIdx.y == 0 && blockIdx.x == 0 && threadIdx.x < NE) count[threadIdx.x] = 0;
  const float* in = blockIdx.y ? in2 : in1;
  __half* out = blockIdx.y ? out2 : out1;
  int i = (blockIdx.x * 256 + threadIdx.x) * 8;
  if (i >= n) return;
  float4 a = *(const float4*)(in + i);
  float4 b = *(const float4*)(in + i + 4);
  uint4 o;
  o.x = packh2(a.x, a.y);
  o.y = packh2(a.z, a.w);
  o.z = packh2(b.x, b.y);
  o.w = packh2(b.z, b.w);
  *(uint4*)(out + i) = o;
}

// ---------------- LayerNorm (LN1: fp16 hi/lo) ----------------
__global__ void ln_kernel(const float* __restrict__ in, const float* __restrict__ gam,
                          const float* __restrict__ bet,
                          __half* __restrict__ oh, __half* __restrict__ ol) {
  __shared__ float red[256];
  int row = blockIdx.x, tid = threadIdx.x;
  const float* x = in + (size_t)row * DIM;
  float v0 = x[tid], v1 = x[tid+256], v2 = x[tid+512];
  red[tid] = v0+v1+v2; __syncthreads();
  for (int o=128;o;o>>=1){ if (tid<o) red[tid]+=red[tid+o]; __syncthreads(); }
  float mean = red[0] * (1.0f/DIM);
  __syncthreads();
  float d0=v0-mean, d1=v1-mean, d2=v2-mean;
  red[tid] = d0*d0+d1*d1+d2*d2; __syncthreads();
  for (int o=128;o;o>>=1){ if (tid<o) red[tid]+=red[tid+o]; __syncthreads(); }
  float r = rsqrtf(red[0]*(1.0f/DIM) + 1e-5f);
  size_t base = (size_t)row * DIM;
  #pragma unroll
  for (int j = 0; j < 3; j++) {
    int c = tid + j*256;
    float d = (j==0) ? d0 : (j==1) ? d1 : d2;
    float v = d*r*gam[c] + bet[c];
    __half h = __float2half_rn(v);
    oh[base + c] = h;
    ol[base + c] = __float2half_rn(v - __half2float(h));
  }
}

// ---------- Fused LN2 + router ----------
__global__ void ln2_router(const float* __restrict__ in, const float* __restrict__ gam,
                           const float* __restrict__ bet, const float* __restrict__ Wr,
                           __half* __restrict__ oh, float* __restrict__ ocopy,
                           int* __restrict__ bucket, float* __restrict__ pairw,
                           int* __restrict__ count) {
  __shared__ float red[256];
  __shared__ float part[8][NE];
  int row = blockIdx.x, tid = threadIdx.x;
  int wid = tid >> 5, lane = tid & 31;
  const float* x = in + (size_t)row * DIM;
  float v0 = x[tid], v1 = x[tid+256], v2 = x[tid+512];
  red[tid] = v0+v1+v2; __syncthreads();
  for (int o=128;o;o>>=1){ if (tid<o) red[tid]+=red[tid+o]; __syncthreads(); }
  float mean = red[0] * (1.0f/DIM);
  __syncthreads();
  float d0=v0-mean, d1=v1-mean, d2=v2-mean;
  red[tid] = d0*d0+d1*d1+d2*d2; __syncthreads();
  for (int o=128;o;o>>=1){ if (tid<o) red[tid]+=red[tid+o]; __syncthreads(); }
  float r = rsqrtf(red[0]*(1.0f/DIM) + 1e-5f);
  size_t base = (size_t)row * DIM;
  float ln[3];
  #pragma unroll
  for (int j = 0; j < 3; j++) {
    int c = tid + j*256;
    float raw = (j==0) ? v0 : (j==1) ? v1 : v2;
    float d = (j==0) ? d0 : (j==1) ? d1 : d2;
    float v = d*r*gam[c] + bet[c];
    ln[j] = v;
    ocopy[base + c] = raw;
    oh[base + c] = __float2half_rn(v);
  }
  float lg[NE];
  #pragma unroll
  for (int e = 0; e < NE; e++) {
    lg[e] = ln[0]*Wr[tid*NE + e] + ln[1]*Wr[(tid+256)*NE + e] + ln[2]*Wr[(tid+512)*NE + e];
    #pragma unroll
    for (int off = 16; off; off >>= 1) lg[e] += __shfl_xor_sync(0xffffffffu, lg[e], off);
  }
  if (lane == 0) {
    #pragma unroll
    for (int e = 0; e < NE; e++) part[wid][e] = lg[e];
  }
  __syncthreads();
  if (tid == 0) {
    float L[NE];
    #pragma unroll
    for (int e = 0; e < NE; e++) {
      float s = 0.f;
      #pragma unroll
      for (int w = 0; w < 8; w++) s += part[w][e];
      L[e] = s;
    }
    int i0 = 0;
    #pragma unroll
    for (int e = 1; e < NE; e++) if (L[e] > L[i0]) i0 = e;
    int i1 = (i0 == 0) ? 1 : 0;
    #pragma unroll
    for (int e = 0; e < NE; e++) { if (e == i0) continue; if (L[e] > L[i1]) i1 = e; }
    float w0 = 1.f / (1.f + expf(L[i1] - L[i0]));
    float w1 = 1.f - w0;
    int p0 = row*2, p1 = row*2 + 1;
    pairw[p0] = w0; pairw[p1] = w1;
    int q0 = atomicAdd(&count[i0], 1); bucket[i0*NPAIR + q0] = p0;
    int q1 = atomicAdd(&count[i1], 1); bucket[i1*NPAIR + q1] = p1;
  }
}

extern "C" void kernel_launch(void* const* d_in, const int* in_sizes, int n_in,
                              void* d_out, int out_size) {
  const float* x       = (const float*)d_in[0];
  const float* Wqkv    = (const float*)d_in[1];
  const float* Wproj   = (const float*)d_in[2];
  const float* Wrouter = (const float*)d_in[3];
  const float* W1      = (const float*)d_in[4];
  const float* W2      = (const float*)d_in[5];
  const float* ln1g    = (const float*)d_in[6];
  const float* ln1b    = (const float*)d_in[7];
  const float* ln2g    = (const float*)d_in[8];
  const float* ln2b    = (const float*)d_in[9];
  float* out = (float*)d_out;

  Scratch* s = nullptr;
  cudaGetSymbolAddress((void**)&s, g_s);

  cudaFuncSetAttribute(attn_tc, cudaFuncAttributeMaxDynamicSharedMemorySize, AT_SMEM);
  cudaFuncSetAttribute(gemm_split<0>, cudaFuncAttributeMaxDynamicSharedMemorySize, GSMEM_SPLIT);
  cudaFuncSetAttribute(gemm_split<1>, cudaFuncAttributeMaxDynamicSharedMemorySize, GSMEM_SPLIT);
  cudaFuncSetAttribute(gemm_moe<2>, cudaFuncAttributeMaxDynamicSharedMemorySize, GSMEM_MOE);
  cudaFuncSetAttribute(gemm_moe<3>, cudaFuncAttributeMaxDynamicSharedMemorySize, GSMEM_MOE);

  dim3 tb(32, 8);
  transpose_split2<<<dim3(QKVN/32, DIM/32, 2), tb>>>(Wqkv, s->Wqkvth, s->Wqkvtl,
                                                     Wproj, s->Wprojth, s->Wprojtl);
  convert_h2<<<dim3((NE*DIM*FFD)/2048, 2), 256>>>(W1, s->W1h, W2, s->W2h, NE*DIM*FFD, s->count);

  // x -> ln1 -> qkv(fp16 hi/lo, Q scaled) -> attention(TC) -> proj+residual -> x1
  ln_kernel<<<NTOK, 256>>>(x, ln1g, ln1b, s->xln1h, s->xln1l);
  gemm_split<0><<<dim3(QKVN/128, NTOK/128, 1), 256, GSMEM_SPLIT>>>(
      s->xln1h, s->xln1l, s->Wqkvth, s->Wqkvtl, nullptr, s->qkvh, s->qkvl,
      NTOK, QKVN, DIM, nullptr);
  attn_tc<<<dim3(TSEQ/128, NH, NB), 256, AT_SMEM>>>(s->qkvh, s->qkvl, s->attnh, s->attnl);
  gemm_split<1><<<dim3(DIM/128, NTOK/128, 1), 256, GSMEM_SPLIT>>>(
      s->attnh, s->attnl, s->Wprojth, s->Wprojtl, s->x1, nullptr, nullptr,
      NTOK, DIM, DIM, x);

  // x1 -> fused LN2+router (copies x1 into out) -> MoE (down accumulates into out)
  ln2_router<<<NTOK, 256>>>(s->x1, ln2g, ln2b, Wrouter, s->xln2h, out,
                            s->bucket, s->pairw, s->count);
  gemm_moe<2><<<dim3(FFD/128, NPAIR/128, NE), 256, GSMEM_MOE>>>(
      s->xln2h, s->W1h, nullptr, s->Hh, FFD, DIM, s->bucket, s->count, nullptr);
  gemm_moe<3><<<dim3(DIM/128, NPAIR/128, NE), 256, GSMEM_MOE>>>(
      s->Hh, s->W2h, out, nullptr, DIM, FFD, s->bucket, s->count, s->pairw);
}